// round 13
// baseline (speedup 1.0000x reference)
#include <cuda_runtime.h>
#include <cstdint>
#include <math.h>

// Problem constants: N=9 board, C=81 cells.
#define CC 81
#define ND 17            // dy,dx in [-8,8]
#define NDIR (ND*ND)     // 289 distinct direction vectors

// ===========================================================================
// Compile-time geometry in CELL space (fp32 decision pipeline identical to the
// round-6/9/11/12 verified tables; rel_err measured 8.35e-4):
//   ent[a][c]:  cone mask (bit d set iff key[d]<key[c] at center a AND fp32
//               angle sep of directions (a->d),(a->c) < 45) + base weight.
//   tent[a][b]: transposed cone (bit c set iff b is in cone of ent[a][c]).
// ===========================================================================
constexpr double CPI = 3.14159265358979323846264338327950288;

constexpr double c_sqrt(double x) {
    if (x <= 0.0) return 0.0;
    double g = (x < 1.0) ? 1.0 : x;
    for (int i = 0; i < 30; i++) g = 0.5 * (g + x / g);
    return g;
}
constexpr double c_atan01(double z) {
    double r = z;
    for (int i = 0; i < 3; i++) r = r / (1.0 + c_sqrt(1.0 + r * r));
    double r2 = r * r, s = 0.0, term = r;
    for (int k = 0; k < 13; k++) {
        s += ((k & 1) ? -term : term) / (double)(2 * k + 1);
        term *= r2;
    }
    return 8.0 * s;
}
constexpr double c_atan2(double y, double x) {
    if (x == 0.0) return (y > 0.0) ? CPI * 0.5 : (y < 0.0 ? -CPI * 0.5 : 0.0);
    double ay = (y < 0.0) ? -y : y, ax = (x < 0.0) ? -x : x;
    double az = ay / ax;
    double a  = (az <= 1.0) ? c_atan01(az) : (CPI * 0.5 - c_atan01(1.0 / az));
    if (x < 0.0) a = CPI - a;
    return (y < 0.0) ? -a : a;
}

struct alignas(16) Ent  { unsigned long long lo; unsigned int hi; float base; };
struct alignas(16) Tent { unsigned long long lo; unsigned int hi; unsigned int pad; };

struct Tables {
    Ent  e [CC][CC];   // [center a][cell c]
    Tent tr[CC][CC];   // [center a][cell b]
};

constexpr Tables make_tables() {
    Tables tb{};
    float angt[NDIR] = {};
    for (int dy = -8; dy <= 8; dy++)
        for (int dx = -8; dx <= 8; dx++) {
            double da = c_atan2((double)(-dy), (double)dx);
            float raw = (float)da * 57.295779513082323f;
            angt[(dy + 8) * ND + (dx + 8)] = (raw > 0.0f) ? raw : raw + 360.0f;
        }
    unsigned long long adj[NDIR][5] = {};
    for (int u = 0; u < NDIR; u++)
        for (int v = 0; v < NDIR; v++) {
            float ad = angt[u] - angt[v];
            if (ad < 0.0f) ad = -ad;
            if (ad > 180.0f) ad = 360.0f - ad;
            if (ad < 45.0f) adj[u][v >> 6] |= 1ull << (v & 63);
        }
    for (int a = 0; a < CC; a++) {
        int ay = a / 9, ax = a % 9;
        int key[CC] = {}, dir[CC] = {};
        for (int c = 0; c < CC; c++) {
            int dy = c / 9 - ay, dx = c % 9 - ax;
            key[c] = (dy * dy + dx * dx) * CC + c;   // stable argsort key
            dir[c] = (dy + 8) * ND + (dx + 8);
        }
        for (int c = 0; c < CC; c++) {
            float dist = (float)c_sqrt((double)(key[c] / CC));
            float b_ = (12.727922061357855f - dist) / 12.727922061357855f;
            if (b_ < 0.5f) b_ = b_ * 0.5f;
            tb.e[a][c].base = b_;
            const unsigned long long* row = adj[dir[c]];
            for (int d = 0; d < CC; d++) {
                if (key[d] < key[c] && ((row[dir[d] >> 6] >> (dir[d] & 63)) & 1ull)) {
                    if (d < 64) tb.e[a][c].lo |= 1ull << d;
                    else        tb.e[a][c].hi |= 1u  << (d - 64);
                    // transposed: cone[a][c] contains d  =>  tent[a][d] bit c
                    if (c < 64) tb.tr[a][d].lo |= 1ull << c;
                    else        tb.tr[a][d].hi |= 1u  << (c - 64);
                }
            }
        }
    }
    return tb;
}

__device__ constexpr Tables d_tab = make_tables();

// Persistent state (zero-initialized at load; the last block restores zeros,
// so every graph replay starts from identical state).
__device__ float g_acc3[3][CC];   // 3-way-spread accumulators (less L2-atomic
                                  // same-address serialization: ~9 adds/addr)
__device__ int   g_sub[9];        // hierarchical completion: 9 sub-counters
__device__ int   g_master = 0;    //   + one master (9 arrivals each)

// Exact 2^-k for integer k (attainable k <= 54): no MUFU, 2 ALU ops.
__device__ __forceinline__ float exp2i_neg(int k) {
    return __int_as_float((127 - k) << 23);
}

// ===========================================================================
// One block per CENTER a (a-indexed memory pattern: each block reads only its
// own two 1.3 KB table rows, coalesced, prefetched upfront).
// Empty center a contributes to each empty b != a:
//    C0(a) + 0.5*T(a,b) + selfT(a,b)
// accumulated via atomicAdd into g_acc3[a%3][b]. Completion detection is
// hierarchical (9 sub-counters -> master); the final block sums the 3 slices
// in fixed order, writes all 81 outputs (zeros included), and resets state.
// ONE graph node: no memset, deterministic final sum order.
// ===========================================================================
__global__ void __launch_bounds__(96) fused_kernel(const float* __restrict__ board,
                                                   float* __restrict__ out) {
    __shared__ float        negT[CC];
    __shared__ float        warpsum[3];
    __shared__ unsigned int wbe[3], wbneg[3], wbpos[3];
    __shared__ int          isLast;

    const int a    = blockIdx.x;
    const int t    = threadIdx.x;
    const int lane = t & 31, w = t >> 5;

    // Upfront independent prefetches (block-own rows; no barriers before use).
    uint4 e  = make_uint4(0, 0, 0, 0);
    uint4 te = make_uint4(0, 0, 0, 0);
    int   v  = 1;                       // sentinel non-empty for t >= 81
    if (t < CC) {
        e  = *reinterpret_cast<const uint4*>(&d_tab.e [a][t]);
        te = *reinterpret_cast<const uint4*>(&d_tab.tr[a][t]);
        v  = (int)board[t];
    }

    // Warp ballots over cell occupancy.
    unsigned be = __ballot_sync(0xffffffffu, v == 0);
    unsigned bn = __ballot_sync(0xffffffffu, v <  0);
    unsigned bp = __ballot_sync(0xffffffffu, v >  0);
    if (lane == 0) { wbe[w] = be; wbneg[w] = bn; wbpos[w] = bp; }
    __syncthreads();

    const unsigned long long negLo = (unsigned long long)wbneg[0]
                                   | ((unsigned long long)wbneg[1] << 32);
    const unsigned int       negHi = wbneg[2];
    const unsigned long long posLo = (unsigned long long)wbpos[0]
                                   | ((unsigned long long)wbpos[1] << 32);
    const unsigned int       posHi = wbpos[2];
    const bool aEmpty = (a < 64)
        ? (((((unsigned long long)wbe[0]) | ((unsigned long long)wbe[1] << 32)) >> a) & 1ull)
        : ((wbe[2] >> (a - 64)) & 1u);

    float c0c = 0.0f, nT = 0.0f, sT = 0.0f;
    if (aEmpty && t < CC) {
        const unsigned long long lo =
            (unsigned long long)e.x | ((unsigned long long)e.y << 32);
        const unsigned int hi = e.z;
        const float bs = __uint_as_float(e.w);
        if (v > 0) {
            c0c =  bs * exp2i_neg(__popcll(lo & negLo) + __popc(hi & negHi));
        } else if (v < 0) {
            nT  =  bs * exp2i_neg(__popcll(lo & posLo) + __popc(hi & posHi));
            c0c = -nT;
        } else if (t != a) {
            sT  =  bs * exp2i_neg(__popcll(lo & negLo) + __popc(hi & negHi));
        }
    }
    if (t < CC) negT[t] = nT;

    // C0(a): fixed-order 3-warp reduction.
    float red = c0c;
    for (int o = 16; o; o >>= 1) red += __shfl_down_sync(0xffffffffu, red, o);
    if (lane == 0) warpsum[w] = red;
    __syncthreads();                        // publishes negT + warpsum
    const float C0 = warpsum[0] + warpsum[1] + warpsum[2];

    // Per empty candidate b = t: T(a,b) over neg stones in transposed cone.
    if (aEmpty && t < CC && v == 0 && t != a) {
        unsigned long long m  = ((unsigned long long)te.x
                              | ((unsigned long long)te.y << 32)) & negLo;
        unsigned int       m2 = te.z & negHi;
        float Tb = 0.0f;
        while (m)  { int c = __ffsll((long long)m) - 1; Tb += negT[c];      m  &= m  - 1; }
        while (m2) { int c = __ffs((int)m2) - 1;        Tb += negT[c + 64]; m2 &= m2 - 1; }
        atomicAdd(&g_acc3[a % 3][t], C0 + 0.5f * Tb + sT);
    }

    // ---- hierarchical completion: 9 sub-counters -> master -----------------
    __syncthreads();                        // all this block's atomics issued
    if (t == 0) {
        __threadfence();                    // release our g_acc3 updates
        int last = 0;
        int old = atomicAdd(&g_sub[a / 9], 1);
        if (old == 8) {                     // last of this 9-block subgroup
            int m = atomicAdd(&g_master, 1);
            last = (m == 8);                // last subgroup overall
        }
        if (last) __threadfence();          // acquire all g_acc3 updates
        isLast = last;
    }
    __syncthreads();

    if (isLast) {
        if (t < CC) {
            // Volatile L2 reads (L1 flushed per launch; never cached here).
            volatile float* s0 = &g_acc3[0][t];
            volatile float* s1 = &g_acc3[1][t];
            volatile float* s2 = &g_acc3[2][t];
            out[t] = *s0 + *s1 + *s2;       // fixed slice order
            g_acc3[0][t] = 0.0f;            // restore for next replay
            g_acc3[1][t] = 0.0f;
            g_acc3[2][t] = 0.0f;
        }
        if (t < 9) g_sub[t] = 0;
        if (t == 0) g_master = 0;
    }
}

// ---------------------------------------------------------------------------
// kernel_launch: graph-capturable, allocation-free, deterministic.
// Inputs (metadata order): all_coords int32[243], board float32[81].
// ---------------------------------------------------------------------------
extern "C" void kernel_launch(void* const* d_in, const int* in_sizes, int n_in,
                              void* d_out, int out_size) {
    const float* board = nullptr;
    for (int i = 0; i < n_in; i++) {
        if (in_sizes[i] == 81) { board = (const float*)d_in[i]; break; }
    }
    if (!board) board = (const float*)d_in[n_in - 1];

    fused_kernel<<<81, 96>>>(board, (float*)d_out);
}